// round 6
// baseline (speedup 1.0000x reference)
#include <cuda_runtime.h>
#include <math.h>
#include <stdint.h>

#define BB 8
#define NN 2048
#define MM 2048
#define STRIDE 512            /* max sparse entries per row/col in gmem ELL */
#define PAIRS (STRIDE / 2)
#define NITER 100
#define CL 8                  /* CTAs per cluster */
#define NB2 2                 /* batches per cluster (pipelined) */
#define SLICE 256             /* rows/cols owned per CTA per batch */
#define TXB 8448u             /* per-phase incoming bytes: 2048*4 + 64*4 */

#define KFLOOR 1.9287498479639178e-22f   /* fp32(exp(-50)) */
#define MUV    4.8828125e-4f             /* 1/2048 */
#define EPSDIV 1e-8f

static __device__ __forceinline__ float uaf(unsigned x) { return __uint_as_float(x); }

// ---- static device scratch (no runtime allocations allowed) ----
__device__ uint4 g_rell4[(size_t)BB * PAIRS * NN];   // (j, Ktilde)    row-major ELL
__device__ uint4 g_cell4[(size_t)BB * PAIRS * MM];   // (i, Ktilde)    col-major ELL
__device__ uint4 g_eell4[(size_t)BB * PAIRS * NN];   // (j, Ktilde*d)  row-major ELL (emd)
__device__ int   g_ccnt[BB * MM];
__device__ float g_part[BB * CL];

// ---- dynamic SMEM (~93 KB) ----
struct SK {
    float u[NB2][NN];
    float v[NB2][MM];
    float tx[NB2][MM], ty[NB2][MM], tz[NB2][MM];
    float part[NB2][1024];
    float slotsU[NB2][64], slotsV[NB2][64];
    float wred[32];
    float fscale[NB2][2];     // [bb][0]=KFLOOR*S_v  [bb][1]=KFLOOR*S_u
    int   cntR[NB2][SLICE], cntC[NB2][SLICE];
    unsigned long long mbu[NB2], mbv[NB2];
};

// ---- cluster / DSMEM / mbarrier helpers ----
static __device__ __forceinline__ uint32_t smem_u32(const void* p) {
    return (uint32_t)__cvta_generic_to_shared(p);
}
static __device__ __forceinline__ uint32_t mapa_sh(uint32_t addr, uint32_t rank) {
    uint32_t o;
    asm("mapa.shared::cluster.u32 %0, %1, %2;" : "=r"(o) : "r"(addr), "r"(rank));
    return o;
}
static __device__ __forceinline__ void st_async32(uint32_t daddr, unsigned v, uint32_t dmbar) {
    asm volatile("st.async.shared::cluster.mbarrier::complete_tx::bytes.u32 [%0], %1, [%2];"
                 :: "r"(daddr), "r"(v), "r"(dmbar) : "memory");
}
static __device__ __forceinline__ void st_async64(uint32_t daddr, unsigned long long v, uint32_t dmbar) {
    asm volatile("st.async.shared::cluster.mbarrier::complete_tx::bytes.u64 [%0], %1, [%2];"
                 :: "r"(daddr), "l"(v), "r"(dmbar) : "memory");
}
static __device__ __forceinline__ void mb_init(uint32_t mb, uint32_t cnt) {
    asm volatile("mbarrier.init.shared.b64 [%0], %1;" :: "r"(mb), "r"(cnt) : "memory");
}
static __device__ __forceinline__ void mb_expect(uint32_t mb, uint32_t tx) {
    asm volatile("mbarrier.arrive.expect_tx.shared.b64 _, [%0], %1;" :: "r"(mb), "r"(tx) : "memory");
}
static __device__ __forceinline__ void mb_wait(uint32_t mb, uint32_t parity) {
    uint32_t done;
    asm volatile("{\n\t.reg .pred p;\n\t"
                 "mbarrier.try_wait.parity.acquire.cluster.shared::cta.b64 p, [%1], %2;\n\t"
                 "selp.b32 %0, 1, 0, p;\n\t}"
                 : "=r"(done) : "r"(mb), "r"(parity) : "memory");
    while (!done) {
        asm volatile("{\n\t.reg .pred p;\n\t"
                     "mbarrier.try_wait.parity.acquire.cluster.shared::cta.b64 p, [%1], %2, 0x989680;\n\t"
                     "selp.b32 %0, 1, 0, p;\n\t}"
                     : "=r"(done) : "r"(mb), "r"(parity) : "memory");
    }
}
#define CLUSTER_SYNC() do {                                                 \
    asm volatile("barrier.cluster.arrive.aligned;" ::: "memory");           \
    asm volatile("barrier.cluster.wait.aligned;"   ::: "memory");           \
} while (0)

// ---------------------------------------------------------------------------
// One 8-CTA cluster handles TWO batches, software-pipelined so each batch's
// DSMEM broadcast is hidden behind the other batch's gather/compute.
__global__ void __launch_bounds__(1024, 1) __cluster_dims__(CL, 1, 1)
sinkhorn_fused(const float* __restrict__ src, const float* __restrict__ tgt) {
    extern __shared__ char raw[];
    SK* S = (SK*)raw;
    uint32_t crank;
    asm("mov.u32 %0, %%cluster_ctarank;" : "=r"(crank));
    const int tid  = threadIdx.x;
    const int b0   = (blockIdx.x >> 3) * NB2;
    const int row0 = (int)crank * SLICE;
    const int warp = tid >> 5, lane = tid & 31;

    // ---------------- stage 0: targets -> smem, init -------------------------
#pragma unroll
    for (int bb = 0; bb < NB2; bb++) {
        const float* T = tgt + (size_t)(b0 + bb) * MM * 3;
        for (int j = tid; j < MM; j += 1024) {
            S->tx[bb][j] = T[3 * j + 0];
            S->ty[bb][j] = T[3 * j + 1];
            S->tz[bb][j] = T[3 * j + 2];
            S->v[bb][j] = 1.0f;
        }
        if (tid < SLICE) g_ccnt[(b0 + bb) * MM + row0 + tid] = 0;
    }
    if (tid == 0) {
        mb_init(smem_u32(&S->mbu[0]), 1);
        mb_init(smem_u32(&S->mbu[1]), 1);
        mb_init(smem_u32(&S->mbv[0]), 1);
        mb_init(smem_u32(&S->mbv[1]), 1);
        S->fscale[0][0] = KFLOOR * (float)MM;
        S->fscale[1][0] = KFLOOR * (float)MM;
    }
    CLUSTER_SYNC();

    // ---------------- stage 1: build sparse lists (both batches) -------------
#pragma unroll
    for (int bb = 0; bb < NB2; bb++) {
        const int b = b0 + bb;
        const float* Sp = src + (size_t)b * NN * 3;
        uint2* rell2 = (uint2*)(g_rell4 + (size_t)b * PAIRS * NN);
        uint2* eell2 = (uint2*)(g_eell4 + (size_t)b * PAIRS * NN);
        uint2* cell2 = (uint2*)(g_cell4 + (size_t)b * PAIRS * MM);
        for (int ir = warp; ir < SLICE; ir += 32) {
            const int i = row0 + ir;
            const float sx = Sp[3 * i + 0], sy = Sp[3 * i + 1], sz = Sp[3 * i + 2];
            int rbase = 0;
            for (int j0 = 0; j0 < MM; j0 += 32) {
                const int j = j0 + lane;
                float dx = sx - S->tx[bb][j];
                float dy = sy - S->ty[bb][j];
                float dz = sz - S->tz[bb][j];
                float s = fmaf(dx, dx, fmaf(dy, dy, dz * dz));
                bool pred = (s < 0.25f);
                unsigned mask = __ballot_sync(0xffffffffu, pred);
                if (pred) {
                    float d = sqrtf(s);
                    float kt = expf(-100.0f * d) - KFLOOR;
                    int k = rbase + __popc(mask & ((1u << lane) - 1u));
                    if (k < STRIDE) {
                        size_t i2 = ((size_t)(k >> 1) * NN + i) * 2 + (k & 1);
                        rell2[i2] = make_uint2((unsigned)j, __float_as_uint(kt));
                        eell2[i2] = make_uint2((unsigned)j, __float_as_uint(kt * d));
                    }
                    int kc = atomicAdd(&g_ccnt[b * MM + j], 1);
                    if (kc < STRIDE)
                        cell2[((size_t)(kc >> 1) * MM + j) * 2 + (kc & 1)] =
                            make_uint2((unsigned)i, __float_as_uint(kt));
                }
                rbase += __popc(mask);
            }
            int cap = (rbase < STRIDE) ? rbase : STRIDE;
            if (lane == 0) {
                S->cntR[bb][ir] = cap;
                if (cap & 1) {   // zero-pad ELL odd tail (cap==STRIDE is even)
                    size_t i2 = ((size_t)(cap >> 1) * NN + i) * 2 + 1;
                    rell2[i2] = make_uint2(0u, 0u);
                    eell2[i2] = make_uint2(0u, 0u);
                }
            }
        }
    }
    CLUSTER_SYNC();   // cluster-wide col atomics + ELL writes done

    // col counts for own slices + odd-tail pads
    if (tid < SLICE) {
#pragma unroll
        for (int bb = 0; bb < NB2; bb++) {
            int c = g_ccnt[(b0 + bb) * MM + row0 + tid];
            c = (c < STRIDE) ? c : STRIDE;
            S->cntC[bb][tid] = c;
            if (c & 1) {
                uint2* cell2 = (uint2*)(g_cell4 + (size_t)(b0 + bb) * PAIRS * MM);
                cell2[((size_t)(c >> 1) * MM + (row0 + tid)) * 2 + 1] = make_uint2(0u, 0u);
            }
        }
    }
    __syncthreads();

    // ---------------- stage 2: 100 pipelined Sinkhorn iterations -------------
    const int lrow = tid & (SLICE - 1);
    const int sub  = tid >> 8;               // 0..3
    const uint4* prow0 = g_rell4 + (size_t)(b0 + 0) * PAIRS * NN + (row0 + lrow);
    const uint4* prow1 = g_rell4 + (size_t)(b0 + 1) * PAIRS * NN + (row0 + lrow);
    const uint4* pcol0 = g_cell4 + (size_t)(b0 + 0) * PAIRS * MM + (row0 + lrow);
    const uint4* pcol1 = g_cell4 + (size_t)(b0 + 1) * PAIRS * MM + (row0 + lrow);
    const int rnp0 = (S->cntR[0][lrow] + 1) >> 1;
    const int rnp1 = (S->cntR[1][lrow] + 1) >> 1;
    const int cnp0 = (S->cntC[0][lrow] + 1) >> 1;
    const int cnp1 = (S->cntC[1][lrow] + 1) >> 1;
    const uint32_t mbu0 = smem_u32(&S->mbu[0]), mbu1 = smem_u32(&S->mbu[1]);
    const uint32_t mbv0 = smem_u32(&S->mbv[0]), mbv1 = smem_u32(&S->mbv[1]);
    const uint32_t ua0 = smem_u32(&S->u[0][row0 + tid]);
    const uint32_t ua1 = smem_u32(&S->u[1][row0 + tid]);
    const uint32_t va0 = smem_u32(&S->v[0][row0 + tid]);
    const uint32_t va1 = smem_u32(&S->v[1][row0 + tid]);
    const uint32_t sU0 = smem_u32(S->slotsU[0]) + (crank * 8u + (uint32_t)warp) * 4u;
    const uint32_t sU1 = smem_u32(S->slotsU[1]) + (crank * 8u + (uint32_t)warp) * 4u;
    const uint32_t sV0 = smem_u32(S->slotsV[0]) + (crank * 8u + (uint32_t)warp) * 4u;
    const uint32_t sV1 = smem_u32(S->slotsV[1]) + (crank * 8u + (uint32_t)warp) * 4u;

    for (int iter = 0; iter < NITER; iter++) {
        const uint32_t par = (uint32_t)(iter & 1);

        // ======== A0: u0 from v0 ========
        if (tid == 0) mb_expect(mbu0, TXB);
        if (iter) {
            mb_wait(mbv0, par ^ 1u);
            if (tid < 32) {
                float s2 = S->slotsV[0][tid] + S->slotsV[0][tid + 32];
#pragma unroll
                for (int o = 16; o > 0; o >>= 1) s2 += __shfl_xor_sync(0xffffffffu, s2, o);
                if (tid == 0) S->fscale[0][0] = KFLOOR * s2;
            }
        }
        {
            float acc = 0.0f;
#pragma unroll 2
            for (int pk = sub; pk < rnp0; pk += 4) {
                uint4 e = prow0[(size_t)pk * NN];
                acc = fmaf(uaf(e.y), S->v[0][e.x], acc);
                acc = fmaf(uaf(e.w), S->v[0][e.z], acc);
            }
            S->part[0][tid] = acc;
        }
        __syncthreads();
        if (tid < SLICE) {
            float tot = S->part[0][tid] + S->part[0][tid + 256] + S->part[0][tid + 512] + S->part[0][tid + 768];
            float u = MUV / fmaxf(S->fscale[0][0] + tot, EPSDIV);
            float ws = u;
#pragma unroll
            for (int o = 16; o > 0; o >>= 1) ws += __shfl_xor_sync(0xffffffffu, ws, o);
            float uhi = __shfl_down_sync(0xffffffffu, u, 1);
            if (!(tid & 1)) {
                unsigned long long pk = ((unsigned long long)__float_as_uint(uhi) << 32) | __float_as_uint(u);
#pragma unroll
                for (uint32_t r = 0; r < CL; r++) st_async64(mapa_sh(ua0, r), pk, mapa_sh(mbu0, r));
            }
            if (lane == 0) {
#pragma unroll
                for (uint32_t r = 0; r < CL; r++) st_async32(mapa_sh(sU0, r), __float_as_uint(ws), mapa_sh(mbu0, r));
            }
        }

        // ======== A1: u1 from v1 ========
        if (tid == 0) mb_expect(mbu1, TXB);
        if (iter) {
            mb_wait(mbv1, par ^ 1u);
            if (tid < 32) {
                float s2 = S->slotsV[1][tid] + S->slotsV[1][tid + 32];
#pragma unroll
                for (int o = 16; o > 0; o >>= 1) s2 += __shfl_xor_sync(0xffffffffu, s2, o);
                if (tid == 0) S->fscale[1][0] = KFLOOR * s2;
            }
        }
        {
            float acc = 0.0f;
#pragma unroll 2
            for (int pk = sub; pk < rnp1; pk += 4) {
                uint4 e = prow1[(size_t)pk * NN];
                acc = fmaf(uaf(e.y), S->v[1][e.x], acc);
                acc = fmaf(uaf(e.w), S->v[1][e.z], acc);
            }
            S->part[1][tid] = acc;
        }
        __syncthreads();
        if (tid < SLICE) {
            float tot = S->part[1][tid] + S->part[1][tid + 256] + S->part[1][tid + 512] + S->part[1][tid + 768];
            float u = MUV / fmaxf(S->fscale[1][0] + tot, EPSDIV);
            float ws = u;
#pragma unroll
            for (int o = 16; o > 0; o >>= 1) ws += __shfl_xor_sync(0xffffffffu, ws, o);
            float uhi = __shfl_down_sync(0xffffffffu, u, 1);
            if (!(tid & 1)) {
                unsigned long long pk = ((unsigned long long)__float_as_uint(uhi) << 32) | __float_as_uint(u);
#pragma unroll
                for (uint32_t r = 0; r < CL; r++) st_async64(mapa_sh(ua1, r), pk, mapa_sh(mbu1, r));
            }
            if (lane == 0) {
#pragma unroll
                for (uint32_t r = 0; r < CL; r++) st_async32(mapa_sh(sU1, r), __float_as_uint(ws), mapa_sh(mbu1, r));
            }
        }

        // ======== B0: v0 from u0 ========
        if (tid == 0) mb_expect(mbv0, TXB);
        mb_wait(mbu0, par);
        if (tid < 32) {
            float s2 = S->slotsU[0][tid] + S->slotsU[0][tid + 32];
#pragma unroll
            for (int o = 16; o > 0; o >>= 1) s2 += __shfl_xor_sync(0xffffffffu, s2, o);
            if (tid == 0) S->fscale[0][1] = KFLOOR * s2;
        }
        {
            float acc = 0.0f;
#pragma unroll 2
            for (int pk = sub; pk < cnp0; pk += 4) {
                uint4 e = pcol0[(size_t)pk * MM];
                acc = fmaf(uaf(e.y), S->u[0][e.x], acc);
                acc = fmaf(uaf(e.w), S->u[0][e.z], acc);
            }
            S->part[0][tid] = acc;
        }
        __syncthreads();
        if (tid < SLICE) {
            float tot = S->part[0][tid] + S->part[0][tid + 256] + S->part[0][tid + 512] + S->part[0][tid + 768];
            float v = MUV / fmaxf(S->fscale[0][1] + tot, EPSDIV);
            float ws = v;
#pragma unroll
            for (int o = 16; o > 0; o >>= 1) ws += __shfl_xor_sync(0xffffffffu, ws, o);
            float vhi = __shfl_down_sync(0xffffffffu, v, 1);
            if (!(tid & 1)) {
                unsigned long long pk = ((unsigned long long)__float_as_uint(vhi) << 32) | __float_as_uint(v);
#pragma unroll
                for (uint32_t r = 0; r < CL; r++) st_async64(mapa_sh(va0, r), pk, mapa_sh(mbv0, r));
            }
            if (lane == 0) {
#pragma unroll
                for (uint32_t r = 0; r < CL; r++) st_async32(mapa_sh(sV0, r), __float_as_uint(ws), mapa_sh(mbv0, r));
            }
        }

        // ======== B1: v1 from u1 ========
        if (tid == 0) mb_expect(mbv1, TXB);
        mb_wait(mbu1, par);
        if (tid < 32) {
            float s2 = S->slotsU[1][tid] + S->slotsU[1][tid + 32];
#pragma unroll
            for (int o = 16; o > 0; o >>= 1) s2 += __shfl_xor_sync(0xffffffffu, s2, o);
            if (tid == 0) S->fscale[1][1] = KFLOOR * s2;
        }
        {
            float acc = 0.0f;
#pragma unroll 2
            for (int pk = sub; pk < cnp1; pk += 4) {
                uint4 e = pcol1[(size_t)pk * MM];
                acc = fmaf(uaf(e.y), S->u[1][e.x], acc);
                acc = fmaf(uaf(e.w), S->u[1][e.z], acc);
            }
            S->part[1][tid] = acc;
        }
        __syncthreads();
        if (tid < SLICE) {
            float tot = S->part[1][tid] + S->part[1][tid + 256] + S->part[1][tid + 512] + S->part[1][tid + 768];
            float v = MUV / fmaxf(S->fscale[1][1] + tot, EPSDIV);
            float ws = v;
#pragma unroll
            for (int o = 16; o > 0; o >>= 1) ws += __shfl_xor_sync(0xffffffffu, ws, o);
            float vhi = __shfl_down_sync(0xffffffffu, v, 1);
            if (!(tid & 1)) {
                unsigned long long pk = ((unsigned long long)__float_as_uint(vhi) << 32) | __float_as_uint(v);
#pragma unroll
                for (uint32_t r = 0; r < CL; r++) st_async64(mapa_sh(va1, r), pk, mapa_sh(mbv1, r));
            }
            if (lane == 0) {
#pragma unroll
                for (uint32_t r = 0; r < CL; r++) st_async32(mapa_sh(sV1, r), __float_as_uint(ws), mapa_sh(mbv1, r));
            }
        }
    }

    // drain last v broadcasts, then cluster-quiesce
    mb_wait(mbv0, (uint32_t)((NITER - 1) & 1));
    mb_wait(mbv1, (uint32_t)((NITER - 1) & 1));
    CLUSTER_SYNC();

    // ---------------- stage 3: EMD epilogue (both batches) -------------------
#pragma unroll
    for (int bb = 0; bb < NB2; bb++) {
        const int b = b0 + bb;
        const float* Sp = src + (size_t)b * NN * 3;
        const uint4* eell = g_eell4 + (size_t)b * PAIRS * NN;
        float wacc = 0.0f;
        for (int ir = warp; ir < SLICE; ir += 32) {
            const int i = row0 + ir;
            const float sx = Sp[3 * i + 0], sy = Sp[3 * i + 1], sz = Sp[3 * i + 2];
            const float ui = S->u[bb][i];
            float dacc = 0.0f;
            for (int j0 = 0; j0 < MM; j0 += 32) {
                const int j = j0 + lane;
                float dx = sx - S->tx[bb][j];
                float dy = sy - S->ty[bb][j];
                float dz = sz - S->tz[bb][j];
                float s = fmaf(dx, dx, fmaf(dy, dy, dz * dz));
                dacc = fmaf(sqrtf(s), S->v[bb][j], dacc);
            }
            float sacc = 0.0f;
            const int np = (S->cntR[bb][ir] + 1) >> 1;
            const uint4* p = eell + i;
            for (int pp = lane; pp < np; pp += 32) {
                uint4 e = p[(size_t)pp * NN];
                sacc = fmaf(uaf(e.y), S->v[bb][e.x], sacc);
                sacc = fmaf(uaf(e.w), S->v[bb][e.z], sacc);
            }
            float tot = fmaf(KFLOOR, dacc, sacc);
#pragma unroll
            for (int o = 16; o > 0; o >>= 1) tot += __shfl_xor_sync(0xffffffffu, tot, o);
            if (lane == 0) wacc = fmaf(ui, tot, wacc);
        }
        if (lane == 0) S->wred[warp] = wacc;
        __syncthreads();
        if (tid == 0) {
            float s = 0.0f;
            for (int w = 0; w < 32; w++) s += S->wred[w];
            g_part[b * CL + (int)crank] = s;
        }
        __syncthreads();   // wred reuse across batches
    }
}

// ---------------------------------------------------------------------------
__global__ void finalize_kernel(float* out) {
    __shared__ float r[2];
    float s = 0.0f;
    for (int i = threadIdx.x; i < BB * CL; i += 64) s += g_part[i];
#pragma unroll
    for (int o = 16; o > 0; o >>= 1) s += __shfl_xor_sync(0xffffffffu, s, o);
    if ((threadIdx.x & 31) == 0) r[threadIdx.x >> 5] = s;
    __syncthreads();
    if (threadIdx.x == 0) out[0] = (r[0] + r[1]) * (1.0f / BB);
}

// ---------------------------------------------------------------------------
extern "C" void kernel_launch(void* const* d_in, const int* in_sizes, int n_in,
                              void* d_out, int out_size) {
    (void)in_sizes; (void)n_in; (void)out_size;
    const float* src = (const float*)d_in[0];
    const float* tgt = (const float*)d_in[1];
    float* out = (float*)d_out;

    cudaFuncSetAttribute(sinkhorn_fused, cudaFuncAttributeMaxDynamicSharedMemorySize,
                         (int)sizeof(SK));
    sinkhorn_fused<<<(BB / NB2) * CL, 1024, sizeof(SK)>>>(src, tgt);
    finalize_kernel<<<1, 64>>>(out);
}

// round 7
// speedup vs baseline: 1.7310x; 1.7310x over previous
#include <cuda_runtime.h>
#include <math.h>
#include <stdint.h>

#define BB 8
#define NN 2048
#define MM 2048
#define STRIDE 512            /* max sparse entries per row/col in gmem ELL */
#define PAIRS (STRIDE / 2)
#define NITER 100
#define CL 8                  /* CTAs per cluster (= per batch) */
#define SLICE 256             /* rows/cols owned per CTA        */
#define TXB 7200u             /* per-phase incoming: 7*1024 (bulk) + 8*4 (slots) */

#define KFLOOR 1.9287498479639178e-22f   /* fp32(exp(-50)) */
#define MUV    4.8828125e-4f             /* 1/2048 */
#define EPSDIV 1e-8f

static __device__ __forceinline__ float uaf(unsigned x) { return __uint_as_float(x); }

// ---- static device scratch (no runtime allocations allowed) ----
__device__ uint4 g_rell4[(size_t)BB * PAIRS * NN];   // (j, Ktilde)    row-major ELL
__device__ uint4 g_cell4[(size_t)BB * PAIRS * MM];   // (i, Ktilde)    col-major ELL
__device__ uint4 g_eell4[(size_t)BB * PAIRS * NN];   // (j, Ktilde*d)  row-major ELL (emd)
__device__ int   g_ccnt[BB * MM];
__device__ float g_part[BB * CL];

// ---- dynamic SMEM (~47.3 KB) ----
struct SK {
    float u[NN];               // full u, replicated per CTA (16B-aligned: first member)
    float v[MM];
    float tx[MM], ty[MM], tz[MM];
    float part[1024];
    float slotsU[8], slotsV[8];
    float wred[32];
    float fscale[2];           // [0]=KFLOOR*S_v  [1]=KFLOOR*S_u
    int   cntR[SLICE], cntC[SLICE];
    unsigned long long mbu, mbv;
};

// ---- cluster / DSMEM / mbarrier helpers ----
static __device__ __forceinline__ uint32_t smem_u32(const void* p) {
    return (uint32_t)__cvta_generic_to_shared(p);
}
static __device__ __forceinline__ uint32_t mapa_sh(uint32_t addr, uint32_t rank) {
    uint32_t o;
    asm("mapa.shared::cluster.u32 %0, %1, %2;" : "=r"(o) : "r"(addr), "r"(rank));
    return o;
}
static __device__ __forceinline__ void st_async32(uint32_t daddr, unsigned v, uint32_t dmbar) {
    asm volatile("st.async.shared::cluster.mbarrier::complete_tx::bytes.u32 [%0], %1, [%2];"
                 :: "r"(daddr), "r"(v), "r"(dmbar) : "memory");
}
static __device__ __forceinline__ void bulk_s2s(uint32_t dst_cluster, uint32_t src_cta,
                                                uint32_t bytes, uint32_t dmbar_cluster) {
    asm volatile("cp.async.bulk.shared::cluster.shared::cta.mbarrier::complete_tx::bytes "
                 "[%0], [%1], %2, [%3];"
                 :: "r"(dst_cluster), "r"(src_cta), "r"(bytes), "r"(dmbar_cluster) : "memory");
}
static __device__ __forceinline__ void fence_proxy_async_cta() {
    asm volatile("fence.proxy.async.shared::cta;" ::: "memory");
}
static __device__ __forceinline__ void mb_init(uint32_t mb, uint32_t cnt) {
    asm volatile("mbarrier.init.shared.b64 [%0], %1;" :: "r"(mb), "r"(cnt) : "memory");
}
static __device__ __forceinline__ void mb_expect(uint32_t mb, uint32_t tx) {
    asm volatile("mbarrier.arrive.expect_tx.shared.b64 _, [%0], %1;" :: "r"(mb), "r"(tx) : "memory");
}
static __device__ __forceinline__ void mb_wait(uint32_t mb, uint32_t parity) {
    uint32_t done;
    asm volatile("{\n\t.reg .pred p;\n\t"
                 "mbarrier.try_wait.parity.acquire.cluster.shared::cta.b64 p, [%1], %2;\n\t"
                 "selp.b32 %0, 1, 0, p;\n\t}"
                 : "=r"(done) : "r"(mb), "r"(parity) : "memory");
    while (!done) {
        asm volatile("{\n\t.reg .pred p;\n\t"
                     "mbarrier.try_wait.parity.acquire.cluster.shared::cta.b64 p, [%1], %2, 0x989680;\n\t"
                     "selp.b32 %0, 1, 0, p;\n\t}"
                     : "=r"(done) : "r"(mb), "r"(parity) : "memory");
    }
}
#define CLUSTER_SYNC() do {                                                 \
    asm volatile("barrier.cluster.arrive.aligned;" ::: "memory");           \
    asm volatile("barrier.cluster.wait.aligned;"   ::: "memory");           \
} while (0)

// ---------------------------------------------------------------------------
// Fused: build -> 100 Sinkhorn iterations (gmem ELL gather, 1KB bulk DSMEM
// broadcast per peer) -> EMD reduction. One 8-CTA cluster per batch.
__global__ void __launch_bounds__(1024, 1) __cluster_dims__(CL, 1, 1)
sinkhorn_fused(const float* __restrict__ src, const float* __restrict__ tgt) {
    extern __shared__ char raw[];
    SK* S = (SK*)raw;
    uint32_t crank;
    asm("mov.u32 %0, %%cluster_ctarank;" : "=r"(crank));
    const int tid  = threadIdx.x;
    const int b    = blockIdx.x >> 3;
    const int row0 = (int)crank * SLICE;
    const int warp = tid >> 5, lane = tid & 31;

    // ---------------- stage 0: targets -> smem, init -------------------------
    const float* T = tgt + (size_t)b * MM * 3;
    for (int j = tid; j < MM; j += 1024) {
        S->tx[j] = T[3 * j + 0];
        S->ty[j] = T[3 * j + 1];
        S->tz[j] = T[3 * j + 2];
        S->v[j] = 1.0f;
    }
    if (tid < SLICE) g_ccnt[b * MM + row0 + tid] = 0;
    if (tid == 0) {
        mb_init(smem_u32(&S->mbu), 1);
        mb_init(smem_u32(&S->mbv), 1);
        S->fscale[0] = KFLOOR * (float)MM;   // S_v = 2048 at iter 0
    }
    CLUSTER_SYNC();

    // ---------------- stage 1: build (own SLICE rows x all cols) -------------
    const float* Sp = src + (size_t)b * NN * 3;
    uint2* rell2 = (uint2*)(g_rell4 + (size_t)b * PAIRS * NN);
    uint2* eell2 = (uint2*)(g_eell4 + (size_t)b * PAIRS * NN);
    uint2* cell2 = (uint2*)(g_cell4 + (size_t)b * PAIRS * MM);

    for (int ir = warp; ir < SLICE; ir += 32) {
        const int i = row0 + ir;
        const float sx = Sp[3 * i + 0], sy = Sp[3 * i + 1], sz = Sp[3 * i + 2];
        int rbase = 0;
        for (int j0 = 0; j0 < MM; j0 += 32) {
            const int j = j0 + lane;
            float dx = sx - S->tx[j];
            float dy = sy - S->ty[j];
            float dz = sz - S->tz[j];
            float s = fmaf(dx, dx, fmaf(dy, dy, dz * dz));
            bool pred = (s < 0.25f);
            unsigned mask = __ballot_sync(0xffffffffu, pred);
            if (pred) {
                float d = sqrtf(s);
                float kt = expf(-100.0f * d) - KFLOOR;
                int k = rbase + __popc(mask & ((1u << lane) - 1u));
                if (k < STRIDE) {
                    size_t i2 = ((size_t)(k >> 1) * NN + i) * 2 + (k & 1);
                    rell2[i2] = make_uint2((unsigned)j, __float_as_uint(kt));
                    eell2[i2] = make_uint2((unsigned)j, __float_as_uint(kt * d));
                }
                int kc = atomicAdd(&g_ccnt[b * MM + j], 1);
                if (kc < STRIDE)
                    cell2[((size_t)(kc >> 1) * MM + j) * 2 + (kc & 1)] =
                        make_uint2((unsigned)i, __float_as_uint(kt));
            }
            rbase += __popc(mask);
        }
        int cap = (rbase < STRIDE) ? rbase : STRIDE;
        if (lane == 0) {
            S->cntR[ir] = cap;
            if (cap & 1) {   // zero-pad ELL odd tail (cap==STRIDE is even)
                size_t i2 = ((size_t)(cap >> 1) * NN + i) * 2 + 1;
                rell2[i2] = make_uint2(0u, 0u);
                eell2[i2] = make_uint2(0u, 0u);
            }
        }
    }
    CLUSTER_SYNC();   // cluster-wide col atomics + ELL writes done

    if (tid < SLICE) {
        int c = g_ccnt[b * MM + row0 + tid];
        c = (c < STRIDE) ? c : STRIDE;
        S->cntC[tid] = c;
        if (c & 1)
            cell2[((size_t)(c >> 1) * MM + (row0 + tid)) * 2 + 1] = make_uint2(0u, 0u);
    }
    __syncthreads();

    // ---------------- stage 2: 100 Sinkhorn iterations -----------------------
    const int lrow = tid & (SLICE - 1);
    const int sub  = tid >> 8;               // 0..3
    const uint4* prow = g_rell4 + (size_t)b * PAIRS * NN + (row0 + lrow);
    const uint4* pcol = g_cell4 + (size_t)b * PAIRS * MM + (row0 + lrow);
    const int rnp = (S->cntR[lrow] + 1) >> 1;
    const int cnp = (S->cntC[lrow] + 1) >> 1;
    const uint32_t mbu = smem_u32(&S->mbu), mbv = smem_u32(&S->mbv);
    const uint32_t uslice = smem_u32(S->u) + (uint32_t)row0 * 4u;   // my 1KB slice
    const uint32_t vslice = smem_u32(S->v) + (uint32_t)row0 * 4u;
    const uint32_t sU = smem_u32(S->slotsU) + crank * 4u;
    const uint32_t sV = smem_u32(S->slotsV) + crank * 4u;

    for (int iter = 0; iter < NITER; iter++) {
        const uint32_t par = (uint32_t)(iter & 1);

        // ---- phase A: u from v ----
        if (tid == 0) mb_expect(mbu, TXB);
        {
            float acc = 0.0f;
#pragma unroll 2
            for (int pk = sub; pk < rnp; pk += 4) {
                uint4 e = prow[(size_t)pk * NN];
                acc = fmaf(uaf(e.y), S->v[e.x], acc);
                acc = fmaf(uaf(e.w), S->v[e.z], acc);
            }
            S->part[tid] = acc;
        }
        __syncthreads();   // publishes part[] (and fscale[0] from prev phase)
        if (tid < SLICE) {
            float tot = S->part[tid] + S->part[tid + 256] + S->part[tid + 512] + S->part[tid + 768];
            float u = MUV / fmaxf(S->fscale[0] + tot, EPSDIV);
            S->u[row0 + tid] = u;       // local write; bulk-copied to peers below
            float ws = u;
#pragma unroll
            for (int o = 16; o > 0; o >>= 1) ws += __shfl_xor_sync(0xffffffffu, ws, o);
            if (lane == 0) S->wred[warp] = ws;
        }
        __syncthreads();   // u slice + wred visible to senders
        if (tid < 32) {    // warp 0: cluster-sum slot messages (8 x 4B)
            float cs = (lane < 8) ? S->wred[lane] : 0.0f;
#pragma unroll
            for (int o = 16; o > 0; o >>= 1) cs += __shfl_xor_sync(0xffffffffu, cs, o);
            if (lane < 8)
                st_async32(mapa_sh(sU, (uint32_t)lane), __float_as_uint(cs),
                           mapa_sh(mbu, (uint32_t)lane));
        } else if (tid == 32) {   // warp 1: one fence + 7 x 1KB bulk copies
            fence_proxy_async_cta();
#pragma unroll
            for (uint32_t r = 0; r < CL; r++)
                if (r != crank)
                    bulk_s2s(mapa_sh(uslice, r), uslice, (uint32_t)SLICE * 4u,
                             mapa_sh(mbu, r));
        }
        mb_wait(mbu, par);
        if (tid < 32) {   // S_u -> fscale[1]; consumed after phase B's barrier
            float s2 = (lane < 8) ? S->slotsU[lane] : 0.0f;
#pragma unroll
            for (int o = 16; o > 0; o >>= 1) s2 += __shfl_xor_sync(0xffffffffu, s2, o);
            if (lane == 0) S->fscale[1] = KFLOOR * s2;
        }

        // ---- phase B: v from u ----
        if (tid == 0) mb_expect(mbv, TXB);
        {
            float acc = 0.0f;
#pragma unroll 2
            for (int pk = sub; pk < cnp; pk += 4) {
                uint4 e = pcol[(size_t)pk * MM];
                acc = fmaf(uaf(e.y), S->u[e.x], acc);
                acc = fmaf(uaf(e.w), S->u[e.z], acc);
            }
            S->part[tid] = acc;
        }
        __syncthreads();   // publishes part[] and fscale[1]
        if (tid < SLICE) {
            float tot = S->part[tid] + S->part[tid + 256] + S->part[tid + 512] + S->part[tid + 768];
            float v = MUV / fmaxf(S->fscale[1] + tot, EPSDIV);
            S->v[row0 + tid] = v;
            float ws = v;
#pragma unroll
            for (int o = 16; o > 0; o >>= 1) ws += __shfl_xor_sync(0xffffffffu, ws, o);
            if (lane == 0) S->wred[warp] = ws;
        }
        __syncthreads();
        if (tid < 32) {
            float cs = (lane < 8) ? S->wred[lane] : 0.0f;
#pragma unroll
            for (int o = 16; o > 0; o >>= 1) cs += __shfl_xor_sync(0xffffffffu, cs, o);
            if (lane < 8)
                st_async32(mapa_sh(sV, (uint32_t)lane), __float_as_uint(cs),
                           mapa_sh(mbv, (uint32_t)lane));
        } else if (tid == 32) {
            fence_proxy_async_cta();
#pragma unroll
            for (uint32_t r = 0; r < CL; r++)
                if (r != crank)
                    bulk_s2s(mapa_sh(vslice, r), vslice, (uint32_t)SLICE * 4u,
                             mapa_sh(mbv, r));
        }
        mb_wait(mbv, par);
        if (tid < 32) {   // S_v -> fscale[0]; consumed after next phase A barrier
            float s2 = (lane < 8) ? S->slotsV[lane] : 0.0f;
#pragma unroll
            for (int o = 16; o > 0; o >>= 1) s2 += __shfl_xor_sync(0xffffffffu, s2, o);
            if (lane == 0) S->fscale[0] = KFLOOR * s2;
        }
    }

    CLUSTER_SYNC();   // everyone passed final waits: all peer traffic delivered

    // ---------------- stage 3: EMD epilogue ----------------------------------
    // emd_b = sum_i u_i * ( KFLOOR * sum_j d_ij v_j + sum_sparse (K~ d)_ij v_j )
    const uint4* eell = g_eell4 + (size_t)b * PAIRS * NN;
    float wacc = 0.0f;
    for (int ir = warp; ir < SLICE; ir += 32) {
        const int i = row0 + ir;
        const float sx = Sp[3 * i + 0], sy = Sp[3 * i + 1], sz = Sp[3 * i + 2];
        const float ui = S->u[i];
        float dacc = 0.0f;
        for (int j0 = 0; j0 < MM; j0 += 32) {
            const int j = j0 + lane;
            float dx = sx - S->tx[j];
            float dy = sy - S->ty[j];
            float dz = sz - S->tz[j];
            float s = fmaf(dx, dx, fmaf(dy, dy, dz * dz));
            dacc = fmaf(sqrtf(s), S->v[j], dacc);
        }
        float sacc = 0.0f;
        const int np = (S->cntR[ir] + 1) >> 1;
        const uint4* p = eell + i;
        for (int pp = lane; pp < np; pp += 32) {
            uint4 e = p[(size_t)pp * NN];
            sacc = fmaf(uaf(e.y), S->v[e.x], sacc);
            sacc = fmaf(uaf(e.w), S->v[e.z], sacc);
        }
        float tot = fmaf(KFLOOR, dacc, sacc);
#pragma unroll
        for (int o = 16; o > 0; o >>= 1) tot += __shfl_xor_sync(0xffffffffu, tot, o);
        if (lane == 0) wacc = fmaf(ui, tot, wacc);
    }
    if (lane == 0) S->wred[warp] = wacc;
    __syncthreads();
    if (tid == 0) {
        float s = 0.0f;
        for (int w = 0; w < 32; w++) s += S->wred[w];
        g_part[blockIdx.x] = s;
    }
}

// ---------------------------------------------------------------------------
__global__ void finalize_kernel(float* out) {
    __shared__ float r[2];
    float s = 0.0f;
    for (int i = threadIdx.x; i < BB * CL; i += 64) s += g_part[i];
#pragma unroll
    for (int o = 16; o > 0; o >>= 1) s += __shfl_xor_sync(0xffffffffu, s, o);
    if ((threadIdx.x & 31) == 0) r[threadIdx.x >> 5] = s;
    __syncthreads();
    if (threadIdx.x == 0) out[0] = (r[0] + r[1]) * (1.0f / BB);
}

// ---------------------------------------------------------------------------
extern "C" void kernel_launch(void* const* d_in, const int* in_sizes, int n_in,
                              void* d_out, int out_size) {
    (void)in_sizes; (void)n_in; (void)out_size;
    const float* src = (const float*)d_in[0];
    const float* tgt = (const float*)d_in[1];
    float* out = (float*)d_out;

    cudaFuncSetAttribute(sinkhorn_fused, cudaFuncAttributeMaxDynamicSharedMemorySize,
                         (int)sizeof(SK));
    sinkhorn_fused<<<BB * CL, 1024, sizeof(SK)>>>(src, tgt);
    finalize_kernel<<<1, 64>>>(out);
}